// round 16
// baseline (speedup 1.0000x reference)
#include <cuda_runtime.h>
#include <cuda_bf16.h>
#include <cuda_fp16.h>
#include <cstdint>
#include <cstddef>

// ---------------------------------------------------------------------------
// RelAttnBlock: LN -> QKV proj (HMMA bf16-split) -> rel-pos attention (HMMA
// fp16 3-pass split) -> O proj (HMMA). B=8, L=1024, EMB=512, H=8, HD=64
// ---------------------------------------------------------------------------

#define Bq 8
#define Lq 1024
#define EMB 512
#define Hh 8
#define HD 64
#define BSz 1024
#define ROWS (Bq * Lq)          // 8192

typedef __nv_bfloat16 bf16;

// Scratch layout (floats)
#define OFF_Q     ((size_t)0)
#define OFF_K     (OFF_Q    + (size_t)ROWS * EMB)
#define OFF_V     (OFF_K    + (size_t)ROWS * EMB)
#define OFF_HHI   (OFF_V    + (size_t)ROWS * EMB)            // bf16 [8192][512]
#define OFF_HLO   (OFF_HHI  + (size_t)ROWS * EMB / 2)
#define OFF_CHI   (OFF_HLO  + (size_t)ROWS * EMB / 2)
#define OFF_CLO   (OFF_CHI  + (size_t)ROWS * EMB / 2)
#define OFF_WTHI  (OFF_CLO  + (size_t)ROWS * EMB / 2)        // bf16 [2048][512]
#define OFF_WTLO  (OFF_WTHI + (size_t)2048 * 512 / 2)
#define OFF_BIAS  (OFF_WTLO + (size_t)2048 * 512 / 2)
#define OFF_QH    (OFF_BIAS + 2048)                          // fp16 [8192][512]
#define OFF_QL    (OFF_QH   + (size_t)ROWS * EMB / 2)
#define OFF_KH    (OFF_QL   + (size_t)ROWS * EMB / 2)        // fp16, pre-scaled 1/8
#define OFF_KL    (OFF_KH   + (size_t)ROWS * EMB / 2)
#define OFF_ERH   (OFF_KL   + (size_t)ROWS * EMB / 2)        // fp16 [8][1024][64]
#define OFF_ERL   (OFF_ERH  + (size_t)Hh * BSz * HD / 2)
#define OFF_VTH   (OFF_ERL  + (size_t)Hh * BSz * HD / 2)     // fp16 [64][64][1024]
#define OFF_VTL   (OFF_VTH  + (size_t)64 * HD * Lq / 2)
#define SCRATCH_FLOATS (OFF_VTL + (size_t)64 * HD * Lq / 2)

__device__ float g_scratch[SCRATCH_FLOATS];

// ---------------------------------------------------------------------------
// PTX helpers
// ---------------------------------------------------------------------------
__device__ __forceinline__ uint32_t smem_u32(const void* p) {
    uint32_t a;
    asm("{ .reg .u64 t; cvta.to.shared.u64 t, %1; cvt.u32.u64 %0, t; }"
        : "=r"(a) : "l"(p));
    return a;
}

#define CP_ASYNC16(saddr, gptr) \
    asm volatile("cp.async.cg.shared.global [%0], [%1], 16;" \
                 :: "r"(saddr), "l"(gptr) : "memory")
#define CP_COMMIT() asm volatile("cp.async.commit_group;" ::: "memory")
#define CP_WAIT1()  asm volatile("cp.async.wait_group 1;" ::: "memory")
#define CP_WAIT0()  asm volatile("cp.async.wait_group 0;" ::: "memory")

#define LDSM4(r0, r1, r2, r3, addr) \
    asm volatile("ldmatrix.sync.aligned.m8n8.x4.shared.b16 {%0,%1,%2,%3}, [%4];" \
                 : "=r"(r0), "=r"(r1), "=r"(r2), "=r"(r3) : "r"(addr))

#define LDSM2(r0, r1, addr) \
    asm volatile("ldmatrix.sync.aligned.m8n8.x2.shared.b16 {%0,%1}, [%2];" \
                 : "=r"(r0), "=r"(r1) : "r"(addr))

#define MMA16816(c, a0, a1, a2, a3, b0, b1) \
    asm volatile("mma.sync.aligned.m16n8k16.row.col.f32.bf16.bf16.f32 " \
                 "{%0,%1,%2,%3}, {%4,%5,%6,%7}, {%8,%9}, {%0,%1,%2,%3};" \
                 : "+f"((c)[0]), "+f"((c)[1]), "+f"((c)[2]), "+f"((c)[3]) \
                 : "r"(a0), "r"(a1), "r"(a2), "r"(a3), "r"(b0), "r"(b1))

#define MMAH(c, a, b0, b1) \
    asm volatile("mma.sync.aligned.m16n8k16.row.col.f32.f16.f16.f32 " \
                 "{%0,%1,%2,%3}, {%4,%5,%6,%7}, {%8,%9}, {%0,%1,%2,%3};" \
                 : "+f"((c)[0]), "+f"((c)[1]), "+f"((c)[2]), "+f"((c)[3]) \
                 : "r"((a)[0]), "r"((a)[1]), "r"((a)[2]), "r"((a)[3]), \
                   "r"(b0), "r"(b1))

// ---------------------------------------------------------------------------
// LayerNorm -> bf16 hi/lo split outputs
// ---------------------------------------------------------------------------
__global__ void ln_kernel(const float* __restrict__ x,
                          const float* __restrict__ gamma,
                          const float* __restrict__ beta,
                          bf16* __restrict__ hhi,
                          bf16* __restrict__ hlo)
{
    __shared__ float wsum[4], wsq[4];
    int row = blockIdx.x;
    int tid = threadIdx.x;
    const float4 v = *(const float4*)(x + (size_t)row * EMB + tid * 4);

    float s  = v.x + v.y + v.z + v.w;
    float sq = v.x * v.x + v.y * v.y + v.z * v.z + v.w * v.w;
    #pragma unroll
    for (int off = 16; off > 0; off >>= 1) {
        s  += __shfl_xor_sync(0xffffffffu, s,  off);
        sq += __shfl_xor_sync(0xffffffffu, sq, off);
    }
    int warp = tid >> 5;
    if ((tid & 31) == 0) { wsum[warp] = s; wsq[warp] = sq; }
    __syncthreads();
    float S  = wsum[0] + wsum[1] + wsum[2] + wsum[3];
    float SQ = wsq[0] + wsq[1] + wsq[2] + wsq[3];

    float mu  = S * (1.0f / EMB);
    float var = SQ * (1.0f / EMB) - mu * mu;
    float rinv = rsqrtf(var + 1e-5f);

    int c = tid * 4;
    float o[4];
    o[0] = (v.x - mu) * rinv * gamma[c + 0] + beta[c + 0];
    o[1] = (v.y - mu) * rinv * gamma[c + 1] + beta[c + 1];
    o[2] = (v.z - mu) * rinv * gamma[c + 2] + beta[c + 2];
    o[3] = (v.w - mu) * rinv * gamma[c + 3] + beta[c + 3];

    __nv_bfloat162 hp[2], lp[2];
    #pragma unroll
    for (int i = 0; i < 2; i++) {
        bf16 h0 = __float2bfloat16(o[2 * i]);
        bf16 h1 = __float2bfloat16(o[2 * i + 1]);
        bf16 l0 = __float2bfloat16(o[2 * i]     - __bfloat162float(h0));
        bf16 l1 = __float2bfloat16(o[2 * i + 1] - __bfloat162float(h1));
        hp[i].x = h0; hp[i].y = h1;
        lp[i].x = l0; lp[i].y = l1;
    }
    size_t base = (size_t)row * EMB + c;
    *(__nv_bfloat162*)(hhi + base)     = hp[0];
    *(__nv_bfloat162*)(hhi + base + 2) = hp[1];
    *(__nv_bfloat162*)(hlo + base)     = lp[0];
    *(__nv_bfloat162*)(hlo + base + 2) = lp[1];
}

// ---------------------------------------------------------------------------
// Weight transpose + bf16 split
// ---------------------------------------------------------------------------
__global__ void wt_convert_kernel(const float* __restrict__ Wq,
                                  const float* __restrict__ Wk,
                                  const float* __restrict__ Wv,
                                  const float* __restrict__ Wo,
                                  bf16* __restrict__ wthi,
                                  bf16* __restrict__ wtlo)
{
    __shared__ float t[32][33];
    int z  = blockIdx.z;
    const float* W = (z == 0) ? Wq : (z == 1) ? Wk : (z == 2) ? Wv : Wo;
    int n0 = blockIdx.x * 32;
    int k0 = blockIdx.y * 32;
    int tx = threadIdx.x, ty = threadIdx.y;

    for (int r = ty; r < 32; r += 8)
        t[r][tx] = W[(size_t)(k0 + r) * EMB + n0 + tx];
    __syncthreads();
    for (int r = ty; r < 32; r += 8) {
        float val = t[tx][r];
        bf16 h = __float2bfloat16(val);
        bf16 l = __float2bfloat16(val - __bfloat162float(h));
        size_t idx = (size_t)(z * 512 + n0 + r) * EMB + k0 + tx;
        wthi[idx] = h;
        wtlo[idx] = l;
    }
}

__global__ void bias_gather_kernel(const float* __restrict__ bq,
                                   const float* __restrict__ bk,
                                   const float* __restrict__ bv,
                                   const float* __restrict__ bo,
                                   float* __restrict__ out)
{
    int i = blockIdx.x * 256 + threadIdx.x;
    if (i >= 2048) return;
    int sel = i >> 9;
    const float* b = (sel == 0) ? bq : (sel == 1) ? bk : (sel == 2) ? bv : bo;
    out[i] = b[i & 511];
}

// ---------------------------------------------------------------------------
// q -> fp16 hi/lo ; k -> fp16 hi/lo, pre-scaled by 1/8
// ---------------------------------------------------------------------------
__global__ void qk_convert_kernel(const float* __restrict__ q,
                                  const float* __restrict__ k,
                                  __half* __restrict__ qh,
                                  __half* __restrict__ ql,
                                  __half* __restrict__ kh,
                                  __half* __restrict__ kl)
{
    size_t i = ((size_t)blockIdx.x * 256 + threadIdx.x) * 4;
    float4 qv = *(const float4*)(q + i);
    {
        __half h0 = __float2half_rn(qv.x), h1 = __float2half_rn(qv.y);
        __half h2 = __float2half_rn(qv.z), h3 = __float2half_rn(qv.w);
        __half l0 = __float2half_rn(qv.x - __half2float(h0));
        __half l1 = __float2half_rn(qv.y - __half2float(h1));
        __half l2 = __float2half_rn(qv.z - __half2float(h2));
        __half l3 = __float2half_rn(qv.w - __half2float(h3));
        __half2 ph0 = __halves2half2(h0, h1), ph1 = __halves2half2(h2, h3);
        __half2 pl0 = __halves2half2(l0, l1), pl1 = __halves2half2(l2, l3);
        *(uint2*)(qh + i) = make_uint2(*(uint32_t*)&ph0, *(uint32_t*)&ph1);
        *(uint2*)(ql + i) = make_uint2(*(uint32_t*)&pl0, *(uint32_t*)&pl1);
    }
    float4 kv = *(const float4*)(k + i);
    {
        float s0 = kv.x * 0.125f, s1 = kv.y * 0.125f;
        float s2 = kv.z * 0.125f, s3 = kv.w * 0.125f;
        __half h0 = __float2half_rn(s0), h1 = __float2half_rn(s1);
        __half h2 = __float2half_rn(s2), h3 = __float2half_rn(s3);
        __half l0 = __float2half_rn(s0 - __half2float(h0));
        __half l1 = __float2half_rn(s1 - __half2float(h1));
        __half l2 = __float2half_rn(s2 - __half2float(h2));
        __half l3 = __float2half_rn(s3 - __half2float(h3));
        __half2 ph0 = __halves2half2(h0, h1), ph1 = __halves2half2(h2, h3);
        __half2 pl0 = __halves2half2(l0, l1), pl1 = __halves2half2(l2, l3);
        *(uint2*)(kh + i) = make_uint2(*(uint32_t*)&ph0, *(uint32_t*)&ph1);
        *(uint2*)(kl + i) = make_uint2(*(uint32_t*)&pl0, *(uint32_t*)&pl1);
    }
}

// Er fp32 [8][1024][64] -> fp16 hi/lo, same layout
__global__ void er_convert_kernel(const float* __restrict__ er,
                                  __half* __restrict__ erh,
                                  __half* __restrict__ erl)
{
    size_t i = ((size_t)blockIdx.x * 256 + threadIdx.x) * 4;
    if (i >= (size_t)Hh * BSz * HD) return;
    float4 v = *(const float4*)(er + i);
    __half h0 = __float2half_rn(v.x), h1 = __float2half_rn(v.y);
    __half h2 = __float2half_rn(v.z), h3 = __float2half_rn(v.w);
    __half l0 = __float2half_rn(v.x - __half2float(h0));
    __half l1 = __float2half_rn(v.y - __half2float(h1));
    __half l2 = __float2half_rn(v.z - __half2float(h2));
    __half l3 = __float2half_rn(v.w - __half2float(h3));
    __half2 ph0 = __halves2half2(h0, h1), ph1 = __halves2half2(h2, h3);
    __half2 pl0 = __halves2half2(l0, l1), pl1 = __halves2half2(l2, l3);
    *(uint2*)(erh + i) = make_uint2(*(uint32_t*)&ph0, *(uint32_t*)&ph1);
    *(uint2*)(erl + i) = make_uint2(*(uint32_t*)&pl0, *(uint32_t*)&pl1);
}

// V fp32 [b][j][h*64+d] -> Vt fp16 hi/lo [(b*8+h)*64 + d][j]
__global__ void vt_convert_kernel(const float* __restrict__ v,
                                  __half* __restrict__ vth,
                                  __half* __restrict__ vtl)
{
    __shared__ float t[32][33];
    int z  = blockIdx.z;           // bh
    int bb = z >> 3, hh = z & 7;
    int l0 = blockIdx.x * 32;
    int d0 = blockIdx.y * 32;
    int tx = threadIdx.x, ty = threadIdx.y;

    for (int r = ty; r < 32; r += 8)
        t[r][tx] = v[((size_t)bb * Lq + l0 + r) * EMB + hh * HD + d0 + tx];
    __syncthreads();
    for (int r = ty; r < 32; r += 8) {
        float val = t[tx][r];
        __half h = __float2half_rn(val);
        __half l = __float2half_rn(val - __half2float(h));
        size_t idx = ((size_t)z * HD + d0 + r) * Lq + l0 + tx;
        vth[idx] = h;
        vtl[idx] = l;
    }
}

// ---------------------------------------------------------------------------
// HMMA bf16 split GEMM, K-chunk 64 (8 chunks), 2-stage cp.async pipeline.
// C[m][n] = sum_k A[m][k]*Wt[n][k] + bias[n]; Ahi*Bhi + Alo*Bhi + Ahi*Blo.
// CTA tile 128x128; 8 warps (4m x 2n). Tiles 128 rows x 64 cols fp16/bf16,
// row stride 144 B (9 granules-coprime padding -> conflict-free ldmatrix).
// ---------------------------------------------------------------------------
#define TILE64_B (128 * 144)          // 18432
#define STG64_B  (4 * TILE64_B)       // 73728
#define GEMM_SMEM_BYTES (2 * STG64_B) // 147456

__global__ __launch_bounds__(256, 1)
void hmma_gemm_kernel(const bf16* __restrict__ Ahi, const bf16* __restrict__ Alo,
                      const bf16* __restrict__ Bhi, const bf16* __restrict__ Blo,
                      const float* __restrict__ bias, int n0,
                      float* __restrict__ o0, float* __restrict__ o1,
                      float* __restrict__ o2, float* __restrict__ o3)
{
    extern __shared__ char smem[];
    uint32_t sbase = smem_u32(smem);

    int tid  = threadIdx.x;
    int wid  = tid >> 5;
    int lane = tid & 31;

    int m0     = blockIdx.y * 128;
    int nglob0 = n0 + blockIdx.x * 128;

    int warp_m = wid & 3;
    int warp_n = wid >> 2;

    float acc[2][8][4];
    #pragma unroll
    for (int mf = 0; mf < 2; mf++)
        #pragma unroll
        for (int nf = 0; nf < 8; nf++)
            #pragma unroll
            for (int e = 0; e < 4; e++) acc[mf][nf][e] = 0.0f;

    int a_row = warp_m * 32 + (lane & 15);
    int a_kg  = lane >> 4;
    int b_row = warp_n * 64 + (lane & 7) + ((lane >> 4) << 3);
    int b_kg  = (lane >> 3) & 1;

    // cp.async map: per tile 128 rows x 8 granules = 1024; 4 per thread.
    #define ISSUE_CHUNK64(c) do {                                             \
        uint32_t st_ = sbase + ((c) & 1) * STG64_B;                           \
        _Pragma("unroll")                                                     \
        for (int i_ = 0; i_ < 4; i_++) {                                      \
            int G = tid + i_ * 256;                                           \
            int row = G >> 3, gg = G & 7;                                     \
            uint32_t so = (uint32_t)(row * 144 + gg * 16);                    \
            size_t ga = (size_t)(m0 + row) * EMB + (c) * 64 + gg * 8;         \
            size_t gb = (size_t)(nglob0 + row) * EMB + (c) * 64 + gg * 8;     \
            CP_ASYNC16(st_ + 0 * TILE64_B + so, Ahi + ga);                    \
            CP_ASYNC16(st_ + 1 * TILE64_B + so, Alo + ga);                    \
            CP_ASYNC16(st_ + 2 * TILE64_B + so, Bhi + gb);                    \
            CP_ASYNC16(st_ + 3 * TILE64_B + so, Blo + gb);                    \
        }                                                                     \
        CP_COMMIT();                                                          \
    } while (0)

    ISSUE_CHUNK64(0);

    for (int c = 0; c < 8; c++) {
        if (c + 1 < 8) { ISSUE_CHUNK64(c + 1); CP_WAIT1(); }
        else           { CP_WAIT0(); }
        __syncthreads();

        uint32_t st = sbase + (c & 1) * STG64_B;
        #pragma unroll
        for (int s = 0; s < 4; s++) {
            uint32_t aoff = (uint32_t)(a_row * 144 + s * 32 + a_kg * 16);
            uint32_t boff = (uint32_t)(b_row * 144 + s * 32 + b_kg * 16);

            uint32_t ah[2][4];
            LDSM4(ah[0][0], ah[0][1], ah[0][2], ah[0][3], st + 0 * TILE64_B + aoff);
            LDSM4(ah[1][0], ah[1][1], ah[1][2], ah[1][3], st + 0 * TILE64_B + aoff + 16 * 144);

            uint32_t bh[4][4];
            #pragma unroll
            for (int p = 0; p < 4; p++)
                LDSM4(bh[p][0], bh[p][1], bh[p][2], bh[p][3],
                      st + 2 * TILE64_B + boff + p * 16 * 144);

            #pragma unroll
            for (int mf = 0; mf < 2; mf++)
                #pragma unroll
                for (int nf = 0; nf < 8; nf++) {
                    int p = nf >> 1, q = (nf & 1) * 2;
                    MMA16816(acc[mf][nf], ah[mf][0], ah[mf][1], ah[mf][2], ah[mf][3],
                             bh[p][q], bh[p][q + 1]);
                }

            uint32_t al[2][4];
            LDSM4(al[0][0], al[0][1], al[0][2], al[0][3], st + 1 * TILE64_B + aoff);
            LDSM4(al[1][0], al[1][1], al[1][2], al[1][3], st + 1 * TILE64_B + aoff + 16 * 144);
            #pragma unroll
            for (int mf = 0; mf < 2; mf++)
                #pragma unroll
                for (int nf = 0; nf < 8; nf++) {
                    int p = nf >> 1, q = (nf & 1) * 2;
                    MMA16816(acc[mf][nf], al[mf][0], al[mf][1], al[mf][2], al[mf][3],
                             bh[p][q], bh[p][q + 1]);
                }

            #pragma unroll
            for (int p = 0; p < 4; p++)
                LDSM4(bh[p][0], bh[p][1], bh[p][2], bh[p][3],
                      st + 3 * TILE64_B + boff + p * 16 * 144);
            #pragma unroll
            for (int mf = 0; mf < 2; mf++)
                #pragma unroll
                for (int nf = 0; nf < 8; nf++) {
                    int p = nf >> 1, q = (nf & 1) * 2;
                    MMA16816(acc[mf][nf], ah[mf][0], ah[mf][1], ah[mf][2], ah[mf][3],
                             bh[p][q], bh[p][q + 1]);
                }
        }
        __syncthreads();
    }

    int sel = nglob0 >> 9;
    float* outp = (sel == 0) ? o0 : (sel == 1) ? o1 : (sel == 2) ? o2 : o3;
    int ncol0 = (nglob0 & 511) + warp_n * 64;
    int g  = lane >> 2;
    int tg = lane & 3;

    #pragma unroll
    for (int mf = 0; mf < 2; mf++) {
        int r0 = m0 + warp_m * 32 + mf * 16 + g;
        #pragma unroll
        for (int nf = 0; nf < 8; nf++) {
            int col = ncol0 + nf * 8 + 2 * tg;
            int bcol = nglob0 - (nglob0 & 511) + col;
            float b0 = bias[bcol], b1 = bias[bcol + 1];
            float2 v0 = make_float2(acc[mf][nf][0] + b0, acc[mf][nf][1] + b1);
            float2 v1 = make_float2(acc[mf][nf][2] + b0, acc[mf][nf][3] + b1);
            *(float2*)(outp + (size_t)r0 * EMB + col)       = v0;
            *(float2*)(outp + (size_t)(r0 + 8) * EMB + col) = v1;
        }
    }
}

// ---------------------------------------------------------------------------
// HMMA attention, fp16 3-pass split on all GEMMs.
// smem: sc 132608 | qs hi/lo 9216 | inv 128 | staging 73728 = 215680
// ---------------------------------------------------------------------------
#define SC_LD    1036
#define SC_BYTES (32 * SC_LD * 4)          // 132608
#define QSH_OFF  SC_BYTES
#define QSL_OFF  (QSH_OFF + 4608)
#define INV_OFF  (QSL_OFF + 4608)          // 141824, 128 B
#define ASTG_OFF (INV_OFF + 128)           // 141952
#define VBH_OFF  ASTG_OFF
#define VBL_OFF  (ASTG_OFF + 17408)
#define PBH_OFF  (ASTG_OFF + 34816)
#define PBL_OFF  (ASTG_OFF + 43520)
#define ATTN_SMEM_BYTES (ASTG_OFF + 2 * 36864)   // 215680

__global__ __launch_bounds__(256, 1)
void attn_kernel(const __half* __restrict__ qh, const __half* __restrict__ ql,
                 const __half* __restrict__ kh, const __half* __restrict__ kl,
                 const __half* __restrict__ erh, const __half* __restrict__ erl,
                 const __half* __restrict__ vth, const __half* __restrict__ vtl,
                 bf16* __restrict__ chi, bf16* __restrict__ clo)
{
    extern __shared__ char smc[];
    float* sc = (float*)smc;
    uint32_t sbase = smem_u32(smc);

    int bh = blockIdx.y;
    int hh = bh & 7;
    int bb = bh >> 3;
    int l0 = blockIdx.x * 32;
    int tid  = threadIdx.x;
    int wid  = tid >> 5;
    int lane = tid & 31;

    // ---- stage q hi/lo into smem (stride 144B) ----
    {
        int r  = tid >> 3;
        int gg = tid & 7;
        size_t gidx = ((size_t)(bb * Lq + l0 + r)) * EMB + hh * HD + gg * 8;
        *(uint4*)(smc + QSH_OFF + r * 144 + gg * 16) = *(const uint4*)(qh + gidx);
        *(uint4*)(smc + QSL_OFF + r * 144 + gg * 16) = *(const uint4*)(ql + gidx);
    }
    __syncthreads();

    // ---- A fragments for q (held through phases E/S) ----
    int a_row = lane & 15;
    int a_kg  = lane >> 4;
    uint32_t qhf[2][4][4], qlf[2][4][4];
    #pragma unroll
    for (int mf = 0; mf < 2; mf++)
        #pragma unroll
        for (int kc = 0; kc < 4; kc++) {
            uint32_t off = (uint32_t)((mf * 16 + a_row) * 144 + kc * 32 + a_kg * 16);
            LDSM4(qhf[mf][kc][0], qhf[mf][kc][1], qhf[mf][kc][2], qhf[mf][kc][3],
                  sbase + QSH_OFF + off);
            LDSM4(qlf[mf][kc][0], qlf[mf][kc][1], qlf[mf][kc][2], qlf[mf][kc][3],
                  sbase + QSL_OFF + off);
        }

    int b_row = wid * 16 + (lane & 7) + ((lane >> 4) << 3);
    int b_kg  = (lane >> 3) & 1;
    int g  = lane >> 2;
    int tg = lane & 3;

    // staging: 128x64 fp16 tiles, stride 144B; hi at +0, lo at +18432.
    #define ISSUE_B(jt_, srcH, srcL, ldsrc) do {                              \
        uint32_t dst = sbase + ASTG_OFF + ((jt_) & 1) * 36864;                \
        _Pragma("unroll")                                                     \
        for (int i_ = 0; i_ < 4; i_++) {                                      \
            int G = tid + i_ * 256;                                           \
            int row = G >> 3, gg_ = G & 7;                                    \
            uint32_t so = (uint32_t)(row * 144 + gg_ * 16);                   \
            size_t gi = (ldsrc);                                              \
            CP_ASYNC16(dst + so,         (srcH) + gi);                        \
            CP_ASYNC16(dst + 18432 + so, (srcL) + gi);                        \
        }                                                                     \
        CP_COMMIT();                                                          \
    } while (0)

    #define ER_IDX ((size_t)(hh * BSz + jt_ * 128 + row)) * HD + gg_ * 8
    #define K_IDX  ((size_t)(bb * Lq + jt_ * 128 + row)) * EMB + hh * HD + gg_ * 8

    // ================= Phase E: QEr -> rotated scatter =================
    { int jt_ = 0; int row, gg_; (void)row; (void)gg_;
      ISSUE_B(0, erh, erl, ER_IDX); }
    for (int jt = 0; jt < 8; jt++) {
        if (jt < 7) { int jt_ = jt + 1; ISSUE_B(jt_, erh, erl, ER_IDX); CP_WAIT1(); }
        else        { CP_WAIT0(); }
        __syncthreads();

        uint32_t kb = sbase + ASTG_OFF + (jt & 1) * 36864;

        float acc[2][2][4];
        #pragma unroll
        for (int mf = 0; mf < 2; mf++)
            #pragma unroll
            for (int nf = 0; nf < 2; nf++)
                #pragma unroll
                for (int e = 0; e < 4; e++) acc[mf][nf][e] = 0.0f;

        #pragma unroll
        for (int kc = 0; kc < 4; kc++) {
            uint32_t off = (uint32_t)(b_row * 144 + kc * 32 + b_kg * 16);
            uint32_t bhr[4], blr[4];
            LDSM4(bhr[0], bhr[1], bhr[2], bhr[3], kb + off);
            LDSM4(blr[0], blr[1], blr[2], blr[3], kb + 18432 + off);
            #pragma unroll
            for (int mf = 0; mf < 2; mf++)
                #pragma unroll
                for (int nf = 0; nf < 2; nf++) {
                    MMAH(acc[mf][nf], qhf[mf][kc], bhr[nf * 2], bhr[nf * 2 + 1]);
                    MMAH(acc[mf][nf], qlf[mf][kc], bhr[nf * 2], bhr[nf * 2 + 1]);
                    MMAH(acc[mf][nf], qhf[mf][kc], blr[nf * 2], blr[nf * 2 + 1]);
                }
        }

        #pragma unroll
        for (int mf = 0; mf < 2; mf++)
            #pragma unroll
            for (int nf = 0; nf < 2; nf++) {
                int pcol = jt * 128 + wid * 16 + nf * 8 + 2 * tg;
                int r1 = mf * 16 + g, r2 = r1 + 8;
                sc[r1 * SC_LD + ((pcol     + l0 + r1) & 1023)] = acc[mf][nf][0];
                sc[r1 * SC_LD + ((pcol + 1 + l0 + r1) & 1023)] = acc[mf][nf][1];
                sc[r2 * SC_LD + ((pcol     + l0 + r2) & 1023)] = acc[mf][nf][2];
                sc[r2 * SC_LD + ((pcol + 1 + l0 + r2) & 1023)] = acc[mf][nf][3];
            }
        __syncthreads();
    }

    // ================= Phase S: scores accumulate =================
    { int jt_ = 0; ISSUE_B(0, kh, kl, K_IDX); }
    for (int jt = 0; jt < 8; jt++) {
        if (jt < 7) { int jt_ = jt + 1; ISSUE_B(jt_, kh, kl, K_IDX); CP_WAIT1(); }
        else        { CP_WAIT0(); }
        __syncthreads();

        uint32_t kb = sbase + ASTG_OFF + (jt & 1) * 36864;

        float acc[2][2][4];
        #pragma unroll
        for (int mf = 0; mf < 2; mf++)
            #pragma unroll
            for (int nf = 0; nf < 2; nf++)
                #pragma unroll
                for (int e = 0; e < 4; e++) acc[mf][nf][e] = 0.0f;

        #pragma unroll
        for (int kc = 0; kc < 4; kc++) {
            uint32_t off = (uint32_t)(b_row * 144 + kc * 32 + b_kg * 16);
            uint32_t bhr[4], blr[4];
            LDSM4(bhr[0], bhr[1], bhr[2], bhr[3], kb + off);
            LDSM4(blr[0], blr[1], blr[2], blr[3], kb + 18432 + off);
            #pragma unroll
            for (int mf = 0; mf < 2; mf++)
                #pragma unroll
                for (int nf = 0; nf < 2; nf++) {
                    MMAH(acc[mf][nf], qhf[mf][kc], bhr[nf * 2], bhr[nf * 2 + 1]);
                    MMAH(acc[mf][nf], qlf[mf][kc], bhr[nf * 2], bhr[nf * 2 + 1]);
                    MMAH(acc[mf][nf], qhf[mf][kc], blr[nf * 2], blr[nf * 2 + 1]);
                }
        }

        #pragma unroll
        for (int mf = 0; mf < 2; mf++)
            #pragma unroll
            for (int nf = 0; nf < 2; nf++) {
                int col = jt * 128 + wid * 16 + nf * 8 + 2 * tg;
                int r1 = mf * 16 + g, r2 = r1 + 8;
                sc[r1 * SC_LD + col]     += acc[mf][nf][0];
                sc[r1 * SC_LD + col + 1] += acc[mf][nf][1];
                sc[r2 * SC_LD + col]     += acc[mf][nf][2];
                sc[r2 * SC_LD + col + 1] += acc[mf][nf][3];
            }
        __syncthreads();
    }

    // ================= Softmax: warp-per-row, float4 passes ===============
    // Leaves exp values UNSCALED in sc; 1/sum stored in inv[row].
    {
        float* invp = (float*)(smc + INV_OFF);
        #pragma unroll
        for (int rr = 0; rr < 4; rr++) {
            int row = wid * 4 + rr;
            float4* srow = (float4*)(sc + row * SC_LD);
            float4 v[8];
            float m = -1e30f;
            #pragma unroll
            for (int u = 0; u < 8; u++) {
                v[u] = srow[lane + u * 32];
                m = fmaxf(m, fmaxf(fmaxf(v[u].x, v[u].y), fmaxf(v[u].z, v[u].w)));
            }
            #pragma unroll
            for (int off = 16; off > 0; off >>= 1)
                m = fmaxf(m, __shfl_xor_sync(0xffffffffu, m, off));

            float ssum = 0.0f;
            #pragma unroll
            for (int u = 0; u < 8; u++) {
                v[u].x = __expf(v[u].x - m);
                v[u].y = __expf(v[u].y - m);
                v[u].z = __expf(v[u].z - m);
                v[u].w = __expf(v[u].w - m);
                ssum += v[u].x + v[u].y + v[u].z + v[u].w;
                srow[lane + u * 32] = v[u];
            }
            #pragma unroll
            for (int off = 16; off > 0; off >>= 1)
                ssum += __shfl_xor_sync(0xffffffffu, ssum, off);

            if (lane == 0) invp[row] = 1.0f / ssum;
        }
    }
    __syncthreads();

    // ================= Phase C: out = P @ V (fp16 3-pass) =================
    float oacc[2][4];
    #pragma unroll
    for (int mf = 0; mf < 2; mf++)
        #pragma unroll
        for (int e = 0; e < 4; e++) oacc[mf][e] = 0.0f;

    int vrow = wid * 8 + (lane & 7);
    int vkg  = (lane >> 3) & 1;

    for (int kt = 0; kt < 8; kt++) {
        // stage Vt hi/lo tiles [64 d][128 j], stride 272B
        {
            #pragma unroll
            for (int i_ = 0; i_ < 4; i_++) {
                int G = tid + i_ * 256;
                int row = G >> 4, gg_ = G & 15;
                uint32_t so = (uint32_t)(row * 272 + gg_ * 16);
                size_t gi = ((size_t)(bh * HD + row)) * Lq + kt * 128 + gg_ * 8;
                CP_ASYNC16(sbase + VBH_OFF + so, vth + gi);
                CP_ASYNC16(sbase + VBL_OFF + so, vtl + gi);
            }
            CP_COMMIT();
        }
        // convert P tile -> fp16 hi/lo (scaled by row inv) while cp.async in flight
        {
            int r = tid >> 3, seg = tid & 7;
            float inv = ((const float*)(smc + INV_OFF))[r];
            const float* srow = sc + r * SC_LD + kt * 128 + seg * 16;
            uint32_t hw[8], lw[8];
            #pragma unroll
            for (int u = 0; u < 8; u++) {
                float2 v = *(const float2*)(srow + u * 2);
                float x = v.x * inv, y = v.y * inv;
                __half a  = __float2half_rn(x);
                __half b  = __float2half_rn(y);
                __half al = __float2half_rn(x - __half2float(a));
                __half bl = __float2half_rn(y - __half2float(b));
                __half2 ph = __halves2half2(a, b);
                __half2 pl = __halves2half2(al, bl);
                hw[u] = *(uint32_t*)&ph;
                lw[u] = *(uint32_t*)&pl;
            }
            *(uint4*)(smc + PBH_OFF + r * 272 + seg * 32)      = make_uint4(hw[0], hw[1], hw[2], hw[3]);
            *(uint4*)(smc + PBH_OFF + r * 272 + seg * 32 + 16) = make_uint4(hw[4], hw[5], hw[6], hw[7]);
            *(uint4*)(smc + PBL_OFF + r * 272 + seg * 32)      = make_uint4(lw[0], lw[1], lw[2], lw[3]);
            *(uint4*)(smc + PBL_OFF + r * 272 + seg * 32 + 16) = make_uint4(lw[4], lw[5], lw[6], lw[7]);
        }
        CP_WAIT0();
        __syncthreads();

        #pragma unroll
        for (int kc = 0; kc < 8; kc++) {
            uint32_t voff = (uint32_t)(vrow * 272 + kc * 32 + vkg * 16);
            uint32_t vh0, vh1, vl0, vl1;
            LDSM2(vh0, vh1, sbase + VBH_OFF + voff);
            LDSM2(vl0, vl1, sbase + VBL_OFF + voff);
            #pragma unroll
            for (int mf = 0; mf < 2; mf++) {
                uint32_t pf[4];
                uint32_t aoff = (uint32_t)((mf * 16 + a_row) * 272 + kc * 32 + a_kg * 16);
                LDSM4(pf[0], pf[1], pf[2], pf[3], sbase + PBH_OFF + aoff);
                MMAH(oacc[mf], pf, vh0, vh1);
                MMAH(oacc[mf], pf, vl0, vl1);
                LDSM4(pf[0], pf[1], pf[2], pf[3], sbase + PBL_OFF + aoff);
                MMAH(oacc[mf], pf, vh0, vh1);
            }
        }
        __syncthreads();
    }

    // epilogue: ctx hi/lo bf16
    #pragma unroll
    for (int mf = 0; mf < 2; mf++) {
        int col = wid * 8 + 2 * tg;
        #pragma unroll
        for (int h2 = 0; h2 < 2; h2++) {
            int r = mf * 16 + g + h2 * 8;
            float v0 = oacc[mf][h2 * 2 + 0];
            float v1 = oacc[mf][h2 * 2 + 1];
            bf16 x0 = __float2bfloat16(v0);
            bf16 x1 = __float2bfloat16(v1);
            bf16 y0 = __float2bfloat16(v0 - __bfloat162float(x0));
            bf16 y1 = __float2bfloat16(v1 - __bfloat162float(x1));
            __nv_bfloat162 hp; hp.x = x0; hp.y = x1;
            __nv_bfloat162 lp; lp.x = y0; lp.y = y1;
            size_t base = ((size_t)(bb * Lq + l0 + r)) * EMB + hh * HD + col;
            *(__nv_bfloat162*)(chi + base) = hp;
            *(__nv_bfloat162*)(clo + base) = lp;
        }
    }
}

// ---------------------------------------------------------------------------
extern "C" void kernel_launch(void* const* d_in, const int* in_sizes, int n_in,
                              void* d_out, int out_size)
{
    const float* x    = (const float*)d_in[0];
    const float* ln_g = (const float*)d_in[1];
    const float* ln_b = (const float*)d_in[2];
    const float* Wq   = (const float*)d_in[3];
    const float* bq   = (const float*)d_in[4];
    const float* Wk   = (const float*)d_in[5];
    const float* bk   = (const float*)d_in[6];
    const float* Wv   = (const float*)d_in[7];
    const float* bv   = (const float*)d_in[8];
    const float* Wo   = (const float*)d_in[9];
    const float* bo   = (const float*)d_in[10];
    const float* Er   = (const float*)d_in[11];
    float* out = (float*)d_out;

    float* scr = nullptr;
    cudaGetSymbolAddress((void**)&scr, g_scratch);
    float*  g_q    = scr + OFF_Q;
    float*  g_k    = scr + OFF_K;
    float*  g_v    = scr + OFF_V;
    bf16*   g_hhi  = (bf16*)(scr + OFF_HHI);
    bf16*   g_hlo  = (bf16*)(scr + OFF_HLO);
    bf16*   g_chi  = (bf16*)(scr + OFF_CHI);
    bf16*   g_clo  = (bf16*)(scr + OFF_CLO);
    bf16*   g_wthi = (bf16*)(scr + OFF_WTHI);
    bf16*   g_wtlo = (bf16*)(scr + OFF_WTLO);
    float*  g_bias = scr + OFF_BIAS;
    __half* g_qh   = (__half*)(scr + OFF_QH);
    __half* g_ql   = (__half*)(scr + OFF_QL);
    __half* g_kh   = (__half*)(scr + OFF_KH);
    __half* g_kl   = (__half*)(scr + OFF_KL);
    __half* g_erh  = (__half*)(scr + OFF_ERH);
    __half* g_erl  = (__half*)(scr + OFF_ERL);
    __half* g_vth  = (__half*)(scr + OFF_VTH);
    __half* g_vtl  = (__half*)(scr + OFF_VTL);

    static bool attr_set = false;
    if (!attr_set) {
        cudaFuncSetAttribute(attn_kernel, cudaFuncAttributeMaxDynamicSharedMemorySize,
                             ATTN_SMEM_BYTES);
        cudaFuncSetAttribute(hmma_gemm_kernel, cudaFuncAttributeMaxDynamicSharedMemorySize,
                             GEMM_SMEM_BYTES);
        attr_set = true;
    }

    // 1. LayerNorm -> h hi/lo (bf16)
    ln_kernel<<<ROWS, 128>>>(x, ln_g, ln_b, g_hhi, g_hlo);

    // 2. Weight transpose+split, bias gather, Er -> fp16 hi/lo
    wt_convert_kernel<<<dim3(16, 16, 4), dim3(32, 8)>>>(Wq, Wk, Wv, Wo, g_wthi, g_wtlo);
    bias_gather_kernel<<<8, 256>>>(bq, bk, bv, bo, g_bias);
    er_convert_kernel<<<512, 256>>>(Er, g_erh, g_erl);

    // 3. QKV projection: HMMA GEMM, N = 1536 -> q,k,v fp32
    hmma_gemm_kernel<<<dim3(12, 64), 256, GEMM_SMEM_BYTES>>>(
        g_hhi, g_hlo, g_wthi, g_wtlo, g_bias, 0, g_q, g_k, g_v, out);

    // 4. fp16 conversions for attention operands (hi/lo)
    qk_convert_kernel<<<4096, 256>>>(g_q, g_k, g_qh, g_ql, g_kh, g_kl);
    vt_convert_kernel<<<dim3(Lq / 32, HD / 32, Bq * Hh), dim3(32, 8)>>>(g_v, g_vth, g_vtl);

    // 5. HMMA attention -> ctx hi/lo (bf16)
    attn_kernel<<<dim3(Lq / 32, Bq * Hh), 256, ATTN_SMEM_BYTES>>>(
        g_qh, g_ql, g_kh, g_kl, g_erh, g_erl, g_vth, g_vtl, g_chi, g_clo);

    // 6. O projection: HMMA GEMM, N in [1536, 2048) -> d_out
    hmma_gemm_kernel<<<dim3(4, 64), 256, GEMM_SMEM_BYTES>>>(
        g_chi, g_clo, g_wthi, g_wtlo, g_bias, 1536, g_q, g_k, g_v, out);
}